// round 16
// baseline (speedup 1.0000x reference)
#include <cuda_runtime.h>
#include <math.h>

// ---------------------------------------------------------------------------
// PhysicalLayer forward, sm_103a.  (Round-16: permutation-free register FFT)
//   Propagation as separable 1024-pt circular convolutions; FO via Bluestein.
//   FFT1024 = FFT32 x twiddle x FFT32 per warp; forward = DIF (bitrev out),
//   inverse = DIT (bitrev in); all rev5 permutations folded into compile-time
//   register/smem/table indices -> no tmp arrays, no spills.
// ---------------------------------------------------------------------------

#define GN 500

typedef unsigned long long u64;

__device__ float2 g_field[GN * GN];
__device__ float2 g_A[GN * GN];
__device__ float2 g_B[GN * GN];
__device__ float  g_tg[GN * GN];
__device__ float2 g_p[1024];
__device__ float2 g_c[1024];
__device__ float2 g_chirp[GN];
__device__ float2 g_W1024[1024];   // e^{-2 pi i t/1024}
__device__ float2 g_Kp[1024];      // FFT1024(q) * 1e-3/1024
__device__ float2 g_Kb[1024];      // FFT1024(c) * 1/1024
__device__ float2 g_W500i[GN];
__device__ float  g_intens[128];
__device__ float  g_canvas[2 * 200 * 200];

__device__ __forceinline__ float2 cmul(float2 a, float2 b) {
    return make_float2(a.x * b.x - a.y * b.y, a.x * b.y + a.y * b.x);
}
__device__ __forceinline__ float2 cmulc(float2 a, float2 b) {  // a * conj(b)
    return make_float2(a.x * b.x + a.y * b.y, a.y * b.x - a.x * b.y);
}

__host__ __device__ __forceinline__ constexpr int rev5(int x) {
    return ((x & 1) << 4) | ((x & 2) << 2) | (x & 4) |
           ((x & 8) >> 2) | ((x & 16) >> 4);
}

__device__ __constant__ const float TC32[16] = {
    1.0f, 0.98078528040323044913f, 0.92387953251128675613f,
    0.83146961230254523708f, 0.70710678118654752440f,
    0.55557023301960222474f, 0.38268343236508977173f,
    0.19509032201612826785f, 0.0f, -0.19509032201612826785f,
    -0.38268343236508977173f, -0.55557023301960222474f,
    -0.70710678118654752440f, -0.83146961230254523708f,
    -0.92387953251128675613f, -0.98078528040323044913f };
__device__ __constant__ const float TS32[16] = {
    0.0f, 0.19509032201612826785f, 0.38268343236508977173f,
    0.55557023301960222474f, 0.70710678118654752440f,
    0.83146961230254523708f, 0.92387953251128675613f,
    0.98078528040323044913f, 1.0f, 0.98078528040323044913f,
    0.92387953251128675613f, 0.83146961230254523708f,
    0.70710678118654752440f, 0.55557023301960222474f,
    0.38268343236508977173f, 0.19509032201612826785f };

// DIF 32-pt FFT, natural input -> BIT-REVERSED output (no permutation).
template <int SIGN>
__device__ __forceinline__ void fft32_dif(float2* r) {
#pragma unroll
    for (int L = 32; L >= 2; L >>= 1) {
        const int half = L >> 1;
        const int step = 32 / L;
#pragma unroll
        for (int b = 0; b < 32; b += L) {
#pragma unroll
            for (int j = 0; j < half; j++) {
                float2 u = r[b + j], v = r[b + j + half];
                r[b + j] = make_float2(u.x + v.x, u.y + v.y);
                float dx = u.x - v.x, dy = u.y - v.y;
                float c = TC32[j * step];
                float s = (float)SIGN * TS32[j * step];
                r[b + j + half] = make_float2(dx * c - dy * s,
                                              dy * c + dx * s);
            }
        }
    }
}

// DIT 32-pt FFT, BIT-REVERSED input -> natural output (no permutation).
template <int SIGN>
__device__ __forceinline__ void fft32_dit(float2* r) {
#pragma unroll
    for (int L = 2; L <= 32; L <<= 1) {
        const int half = L >> 1;
        const int step = 32 / L;
#pragma unroll
        for (int b = 0; b < 32; b += L) {
#pragma unroll
            for (int j = 0; j < half; j++) {
                float2 u = r[b + j];
                float2 tv = r[b + j + half];
                float c = TC32[j * step];
                float s = (float)SIGN * TS32[j * step];
                float2 v = make_float2(tv.x * c - tv.y * s,
                                       tv.y * c + tv.x * s);
                r[b + j] = make_float2(u.x + v.x, u.y + v.y);
                r[b + j + half] = make_float2(u.x - v.x, u.y - v.y);
            }
        }
    }
}

// ---------------- fused prep: tables + zero + field + tg -------------------
__global__ void k_prep(const float* __restrict__ mp,
                       const float* __restrict__ mr,
                       const float2* __restrict__ B1,
                       const float* __restrict__ gam, float sK) {
    int i = blockIdx.x * blockDim.x + threadIdx.x;
    const double PI = 3.14159265358979323846;
    if (i < 1024) {
        float2 v = make_float2(0.f, 0.f);
        if (i < 1000) {
            double alpha = PI * 1.33 / (5.61e-7 * 0.006);
            double x = (double)(i - 499) * 1e-6;
            double th = alpha * x * x;
            double s, c;
            sincos(th, &s, &c);
            v = make_float2((float)c, (float)s);
        }
        g_p[i] = v;
        {
            double ang = -2.0 * PI * (double)i / 1024.0;
            double s, c;
            sincos(ang, &s, &c);
            g_W1024[i] = make_float2((float)c, (float)s);
        }
        {
            float2 cv = make_float2(0.f, 0.f);
            long n = -1;
            if (i < 500) n = i;
            else if (i >= 525) n = 1024 - i;
            if (n >= 0) {
                double th = PI * (double)(n * n) / 500.0;
                double s, c;
                sincos(th, &s, &c);
                cv = make_float2((float)c, (float)s);
            }
            g_c[i] = cv;
        }
    }
    if (i < GN) {
        double th = PI * (double)((long)i * i) / 500.0;
        double s, c;
        sincos(th, &s, &c);
        g_chirp[i] = make_float2((float)c, (float)(-s));
        double ang = -2.0 * PI * (double)i / (double)GN;
        double s2, c2;
        sincos(ang, &s2, &c2);
        g_W500i[i] = make_float2((float)c2, (float)(-s2));
    }
    if (i < 2 * 200 * 200) g_canvas[i] = 0.f;
    if (i < 128) g_intens[i] = 0.f;
    if (i < GN * GN) {
        float s, c;
        sincosf(mp[i], &s, &c);
        float m = mr[i];
        float2 b = B1[i];
        float er = m * c, ei = m * s;
        g_field[i] = make_float2(b.x * er - b.y * ei, b.x * ei + b.y * er);
        int u = i / GN, v2 = i % GN;
        int su = (u + 250) % GN, sv = (v2 + 250) % GN;
        g_tg[i] = sK * gam[su * GN + sv];
    }
}

// ---------------- direct 1024-DFT for the two kernel tables ----------------
__global__ __launch_bounds__(128) void k_tabdft() {
    __shared__ float rx[4], ry[4];
    int k = blockIdx.x;
    int which = blockIdx.y;
    const float2* src = which ? g_c : g_p;
    int t = threadIdx.x;
    int idx = (k * t) & 1023;
    int step = (k * 128) & 1023;
    float ax = 0.f, ay = 0.f;
    for (; t < 1024; t += 128) {
        float2 s = src[t];
        float2 w = g_W1024[idx];
        ax = fmaf(s.x, w.x, ax); ax = fmaf(-s.y, w.y, ax);
        ay = fmaf(s.x, w.y, ay); ay = fmaf(s.y, w.x, ay);
        idx = (idx + step) & 1023;
    }
    int lane = threadIdx.x & 31, wid = threadIdx.x >> 5;
#pragma unroll
    for (int o = 16; o > 0; o >>= 1) {
        ax += __shfl_down_sync(0xffffffffu, ax, o);
        ay += __shfl_down_sync(0xffffffffu, ay, o);
    }
    if (lane == 0) { rx[wid] = ax; ry[wid] = ay; }
    __syncthreads();
    if (threadIdx.x == 0) {
        float Sx = rx[0] + rx[1] + rx[2] + rx[3];
        float Sy = ry[0] + ry[1] + ry[2] + ry[3];
        float sc = which ? (1.0f / 1024.0f) : (1e-3f / 1024.0f);
        if (which) g_Kb[k] = make_float2(Sx * sc, Sy * sc);
        else       g_Kp[k] = make_float2(Sx * sc, Sy * sc);
    }
}

// ---------------- warp-per-row FFT-conv pass -------------------------------
// grid 125 x 128 threads = 500 warps, one row each. mode 0: propagation;
// mode 1: bluestein. All bit-reversals folded into constant indices.
__global__ __launch_bounds__(128) void k_fconv(const float2* __restrict__ in,
                                               float2* __restrict__ out,
                                               int mode) {
    __shared__ float2 sbuf[4][33 * 32];
    int warp = threadIdx.x >> 5;
    int t = threadIdx.x & 31;
    int r = blockIdx.x * 4 + warp;
    float2* sm = sbuf[warp];

    float2 Wt = g_W1024[t];
    float2 a[32];

    // load x[32*n1 + t] (lane t = n2), zero-pad, chirp for bluestein
#pragma unroll
    for (int n1 = 0; n1 < 32; n1++) {
        int idx = n1 * 32 + t;
        float2 v = make_float2(0.f, 0.f);
        if (idx < 500) {
            v = in[(size_t)r * GN + idx];
            if (mode) v = cmul(v, g_chirp[idx]);
        }
        a[n1] = v;
    }

    fft32_dif<-1>(a);                    // pos p holds A_t[rev5(p)]
    // twiddle W1024^{t*k1} + transposed store, k1 natural, reg index rev5(k1)
    {
        float2 w = make_float2(1.f, 0.f);
#pragma unroll
        for (int k1 = 0; k1 < 32; k1++) {
            sm[k1 * 33 + t] = cmul(a[rev5(k1)], w);
            w = cmul(w, Wt);
        }
    }
    __syncwarp();
#pragma unroll
    for (int n2 = 0; n2 < 32; n2++) a[n2] = sm[t * 33 + n2];  // lane = k1

    fft32_dif<-1>(a);                    // pos p holds X[32*rev5(p) + t]

    // pointwise kernel multiply (rev-folded index)
    const float2* K = mode ? g_Kb : g_Kp;
#pragma unroll
    for (int p = 0; p < 32; p++) a[p] = cmul(a[p], K[rev5(p) * 32 + t]);

    fft32_dit<1>(a);                     // bitrev in -> natural: a[n2] = c~[n2]
    // conj twiddle W1024^{-t*n2}, natural order
    {
        float2 w = make_float2(1.f, 0.f);
#pragma unroll
        for (int n2 = 0; n2 < 32; n2++) {
            a[n2] = cmul(a[n2], w);
            w = cmulc(w, Wt);
        }
    }
    __syncwarp();
#pragma unroll
    for (int n2 = 0; n2 < 32; n2++) sm[n2 * 33 + t] = a[n2];
    __syncwarp();
#pragma unroll
    for (int k1 = 0; k1 < 32; k1++) a[k1] = sm[t * 33 + k1];  // lane = n2

    fft32_dif<1>(a);                     // pos p holds y[32*rev5(p) + t]

    // extract + transposed write (rev-folded output index)
    if (mode == 0) {
#pragma unroll
        for (int p = 0; p < 32; p++) {
            int idx = rev5(p) * 32 + t;
            if (idx >= 500 && idx < 1000)
                out[(size_t)(idx - 500) * GN + r] = a[p];
        }
    } else {
#pragma unroll
        for (int p = 0; p < 32; p++) {
            int idx = rev5(p) * 32 + t;
            if (idx < 500)
                out[(size_t)idx * GN + r] = cmul(a[p], g_chirp[idx]);
        }
    }
}

// ---------------- per-emitter intensity: warp-owned emitter ranges ---------
__global__ __launch_bounds__(128) void k_emit(const int* __restrict__ xyz) {
    __shared__ float2 sfo[GN];
    __shared__ float  stg[GN];
    __shared__ float2 sW[GN];
    int u = blockIdx.x;

    const float2* fo = g_B + (size_t)u * GN;   // FO lives in g_B
    const float*  tg = g_tg + (size_t)u * GN;
    for (int i = threadIdx.x; i < GN; i += 128) {
        sfo[i] = fo[i];
        stg[i] = tg[i];
        sW[i]  = g_W500i[i];
    }
    __syncthreads();

    int lane = threadIdx.x & 31;
    int wid = threadIdx.x >> 5;

    for (int e = wid * 32; e < wid * 32 + 32; e++) {
        int x0 = xyz[e * 3 + 0];
        int z = xyz[e * 3 + 2];
        float xf = (float)(x0 - 100);
        int c = 249 + z;
        int idx = (c * lane) % GN;
        int step = (c * 32) % GN;

        float sx = 0.f, sy = 0.f;
        for (int v = lane; v < GN; v += 32) {
            float arg = stg[v] * xf;  // f32 rounding matches reference
            float nq = rintf(arg * 0.15915494309189535f);
            float rr = fmaf(nq, -6.28125f, arg);
            rr = fmaf(nq, -1.9353072e-3f, rr);
            float sn, cs;
            __sincosf(rr, &sn, &cs);
            float2 f = sfo[v];
            float pr = f.x * cs - f.y * sn;
            float pi = f.x * sn + f.y * cs;
            float2 w = sW[idx];
            sx = fmaf(pr, w.x, sx); sx = fmaf(-pi, w.y, sx);
            sy = fmaf(pr, w.y, sy); sy = fmaf(pi, w.x, sy);
            idx += step; if (idx >= GN) idx -= GN;
        }
#pragma unroll
        for (int o = 16; o > 0; o >>= 1) {
            sx += __shfl_down_sync(0xffffffffu, sx, o);
            sy += __shfl_down_sync(0xffffffffu, sy, o);
        }
        if (lane == 0)
            atomicAdd(&g_intens[e], (sx * sx + sy * sy) * 8e-9f);  // 1/500^3
    }
}

// ---------------- scatter psf patches into canvas --------------------------
__global__ void k_scatter(const int* __restrict__ xyz,
                          const float* __restrict__ psf) {
    int tid = blockIdx.x * blockDim.x + threadIdx.x;
    if (tid >= 128 * 961) return;
    int e = tid / 961, p = tid % 961;
    int b = e >> 6;
    int x0 = xyz[e * 3 + 0];
    int y0 = xyz[e * 3 + 1];
    int z = xyz[e * 3 + 2];
    int r = p / 31, cc = p % 31;
    float val = psf[z * 961 + p] * g_intens[e];
    int row = x0 + r - 15;
    int col = y0 + cc - 15;
    atomicAdd(&g_canvas[b * 40000 + row * 200 + col], val);
}

// ---------------- noise model + output -------------------------------------
__global__ void k_final(const float* __restrict__ ng,
                        const float* __restrict__ np_,
                        float* __restrict__ out) {
    int i = blockIdx.x * blockDim.x + threadIdx.x;
    if (i >= 2 * 200 * 200) return;
    float a = g_canvas[i] / 50000.0f + 100.0f;  // imgs3D + UNIF_BG
    float b = a + 100000.0f;
    float t = fmaf(2.0e8f, ng[i], 3.0e8f);
    float inp = b + t;
    if (inp <= 0.0f) inp = 0.0f;
    float noisy = inp + 100.0f * sqrtf(inp) * np_[i];
    if (noisy <= 10.0f) noisy = 1.0f;
    noisy = fminf(noisy, 4.0e9f);
    out[i] = noisy / 4.0e9f;
}

// ---------------------------------------------------------------------------
extern "C" void kernel_launch(void* const* d_in, const int* in_sizes, int n_in,
                              void* d_out, int out_size) {
    const float*  mask_param = (const float*)d_in[0];
    const int*    xyz        = (const int*)d_in[1];
    // d_in[2] = nphotons (unused by reference)
    const float2* B1         = (const float2*)d_in[3];
    // d_in[4] = Q1 (replaced by separable p-vector)
    const float*  mask_real  = (const float*)d_in[5];
    const float*  gamma_c    = (const float*)d_in[6];
    const float*  psf        = (const float*)d_in[7];
    const float*  ngauss     = (const float*)d_in[8];
    const float*  npoiss     = (const float*)d_in[9];
    float*        out        = (float*)d_out;

    double Kd = 2.0 * 1.33 * 3.14159265358979323846 / 5.61e-7;
    float sK = (float)(Kd * 1e-6);

    float2 *fld, *bA, *bB;
    cudaGetSymbolAddress((void**)&fld, g_field);
    cudaGetSymbolAddress((void**)&bA, g_A);
    cudaGetSymbolAddress((void**)&bB, g_B);

    const int BT = 256;

    // fused setup
    k_prep<<<(GN * GN + BT - 1) / BT, BT>>>(mask_param, mask_real, B1,
                                            gamma_c, sK);

    // kernel-spectrum tables Kp, Kb
    k_tabdft<<<dim3(1024, 2), 128>>>();

    // out = 1e-6 T f T^T (two conv passes), FO = F out F^T (two bluestein)
    k_fconv<<<125, 128>>>(fld, bA, 0);
    k_fconv<<<125, 128>>>(bA, bB, 0);
    k_fconv<<<125, 128>>>(bB, bA, 1);
    k_fconv<<<125, 128>>>(bA, bB, 1);   // FO -> g_B

    // per-emitter intensities (4 warps x 32 emitters per block, grid 500)
    k_emit<<<GN, 128>>>(xyz);

    // patches -> canvas
    k_scatter<<<(128 * 961 + BT - 1) / BT, BT>>>(xyz, psf);

    // noise model -> output
    k_final<<<(2 * 200 * 200 + BT - 1) / BT, BT>>>(ngauss, npoiss, out);
}

// round 17
// speedup vs baseline: 1.6787x; 1.6787x over previous
#include <cuda_runtime.h>
#include <math.h>

// ---------------------------------------------------------------------------
// PhysicalLayer forward, sm_103a.  (Round-17: R15 revert + conflict-free
//   XOR-swizzled transposes + templated mode)
//   Propagation as separable 1024-pt circular convolutions; FO via Bluestein.
//   FFT1024 = FFT32 (regs) x twiddle x FFT32 (regs), one warp per row.
// ---------------------------------------------------------------------------

#define GN 500

typedef unsigned long long u64;

__device__ float2 g_field[GN * GN];
__device__ float2 g_A[GN * GN];
__device__ float2 g_B[GN * GN];
__device__ float  g_tg[GN * GN];
__device__ float2 g_p[1024];
__device__ float2 g_c[1024];
__device__ float2 g_chirp[GN];
__device__ float2 g_W1024[1024];   // e^{-2 pi i t/1024}
__device__ float2 g_Kp[1024];      // FFT1024(q) * 1e-3/1024
__device__ float2 g_Kb[1024];      // FFT1024(c) * 1/1024
__device__ float2 g_W500i[GN];
__device__ float  g_intens[128];
__device__ float  g_canvas[2 * 200 * 200];

__device__ __forceinline__ float2 cmul(float2 a, float2 b) {
    return make_float2(a.x * b.x - a.y * b.y, a.x * b.y + a.y * b.x);
}
__device__ __forceinline__ float2 cmulc(float2 a, float2 b) {  // a * conj(b)
    return make_float2(a.x * b.x + a.y * b.y, a.y * b.x - a.x * b.y);
}

__device__ __forceinline__ int rev5(int x) {
    return ((x & 1) << 4) | ((x & 2) << 2) | (x & 4) |
           ((x & 8) >> 2) | ((x & 16) >> 4);
}

// Fully-unrolled 32-point DIF FFT in registers (R15-proven version).
// SIGN=-1: forward; SIGN=+1: inverse (unscaled). Natural order in and out.
template <int SIGN>
__device__ __forceinline__ void fft32(float2* r) {
    const float TC[16] = {
        1.0f, 0.98078528040323044913f, 0.92387953251128675613f,
        0.83146961230254523708f, 0.70710678118654752440f,
        0.55557023301960222474f, 0.38268343236508977173f,
        0.19509032201612826785f, 0.0f, -0.19509032201612826785f,
        -0.38268343236508977173f, -0.55557023301960222474f,
        -0.70710678118654752440f, -0.83146961230254523708f,
        -0.92387953251128675613f, -0.98078528040323044913f };
    const float TS[16] = {
        0.0f, 0.19509032201612826785f, 0.38268343236508977173f,
        0.55557023301960222474f, 0.70710678118654752440f,
        0.83146961230254523708f, 0.92387953251128675613f,
        0.98078528040323044913f, 1.0f, 0.98078528040323044913f,
        0.92387953251128675613f, 0.83146961230254523708f,
        0.70710678118654752440f, 0.55557023301960222474f,
        0.38268343236508977173f, 0.19509032201612826785f };
#pragma unroll
    for (int L = 32; L >= 2; L >>= 1) {
        const int half = L >> 1;
        const int step = 32 / L;
#pragma unroll
        for (int b = 0; b < 32; b += L) {
#pragma unroll
            for (int j = 0; j < half; j++) {
                float2 u = r[b + j], v = r[b + j + half];
                r[b + j] = make_float2(u.x + v.x, u.y + v.y);
                float dx = u.x - v.x, dy = u.y - v.y;
                float c = TC[j * step];
                float s = (float)SIGN * TS[j * step];
                r[b + j + half] = make_float2(dx * c - dy * s,
                                              dy * c + dx * s);
            }
        }
    }
    float2 tmp[32];
#pragma unroll
    for (int k = 0; k < 32; k++) tmp[k] = r[rev5(k)];
#pragma unroll
    for (int k = 0; k < 32; k++) r[k] = tmp[k];
}

// ---------------- fused prep: tables + zero + field + tg -------------------
__global__ void k_prep(const float* __restrict__ mp,
                       const float* __restrict__ mr,
                       const float2* __restrict__ B1,
                       const float* __restrict__ gam, float sK) {
    int i = blockIdx.x * blockDim.x + threadIdx.x;
    const double PI = 3.14159265358979323846;
    if (i < 1024) {
        float2 v = make_float2(0.f, 0.f);
        if (i < 1000) {
            double alpha = PI * 1.33 / (5.61e-7 * 0.006);
            double x = (double)(i - 499) * 1e-6;
            double th = alpha * x * x;
            double s, c;
            sincos(th, &s, &c);
            v = make_float2((float)c, (float)s);
        }
        g_p[i] = v;
        {
            double ang = -2.0 * PI * (double)i / 1024.0;
            double s, c;
            sincos(ang, &s, &c);
            g_W1024[i] = make_float2((float)c, (float)s);
        }
        {
            float2 cv = make_float2(0.f, 0.f);
            long n = -1;
            if (i < 500) n = i;
            else if (i >= 525) n = 1024 - i;
            if (n >= 0) {
                double th = PI * (double)(n * n) / 500.0;
                double s, c;
                sincos(th, &s, &c);
                cv = make_float2((float)c, (float)s);
            }
            g_c[i] = cv;
        }
    }
    if (i < GN) {
        double th = PI * (double)((long)i * i) / 500.0;
        double s, c;
        sincos(th, &s, &c);
        g_chirp[i] = make_float2((float)c, (float)(-s));
        double ang = -2.0 * PI * (double)i / (double)GN;
        double s2, c2;
        sincos(ang, &s2, &c2);
        g_W500i[i] = make_float2((float)c2, (float)(-s2));
    }
    if (i < 2 * 200 * 200) g_canvas[i] = 0.f;
    if (i < 128) g_intens[i] = 0.f;
    if (i < GN * GN) {
        float s, c;
        sincosf(mp[i], &s, &c);
        float m = mr[i];
        float2 b = B1[i];
        float er = m * c, ei = m * s;
        g_field[i] = make_float2(b.x * er - b.y * ei, b.x * ei + b.y * er);
        int u = i / GN, v2 = i % GN;
        int su = (u + 250) % GN, sv = (v2 + 250) % GN;
        g_tg[i] = sK * gam[su * GN + sv];
    }
}

// ---------------- direct 1024-DFT for the two kernel tables ----------------
__global__ __launch_bounds__(128) void k_tabdft() {
    __shared__ float rx[4], ry[4];
    int k = blockIdx.x;
    int which = blockIdx.y;
    const float2* src = which ? g_c : g_p;
    int t = threadIdx.x;
    int idx = (k * t) & 1023;
    int step = (k * 128) & 1023;
    float ax = 0.f, ay = 0.f;
    for (; t < 1024; t += 128) {
        float2 s = src[t];
        float2 w = g_W1024[idx];
        ax = fmaf(s.x, w.x, ax); ax = fmaf(-s.y, w.y, ax);
        ay = fmaf(s.x, w.y, ay); ay = fmaf(s.y, w.x, ay);
        idx = (idx + step) & 1023;
    }
    int lane = threadIdx.x & 31, wid = threadIdx.x >> 5;
#pragma unroll
    for (int o = 16; o > 0; o >>= 1) {
        ax += __shfl_down_sync(0xffffffffu, ax, o);
        ay += __shfl_down_sync(0xffffffffu, ay, o);
    }
    if (lane == 0) { rx[wid] = ax; ry[wid] = ay; }
    __syncthreads();
    if (threadIdx.x == 0) {
        float Sx = rx[0] + rx[1] + rx[2] + rx[3];
        float Sy = ry[0] + ry[1] + ry[2] + ry[3];
        float sc = which ? (1.0f / 1024.0f) : (1e-3f / 1024.0f);
        if (which) g_Kb[k] = make_float2(Sx * sc, Sy * sc);
        else       g_Kp[k] = make_float2(Sx * sc, Sy * sc);
    }
}

// ---------------- warp-per-row FFT-conv pass (templated mode) --------------
// grid 125 x 128 threads = 500 warps, one row each. MODE 0: propagation;
// MODE 1: bluestein. XOR-swizzled transposes (conflict-free both directions).
template <int MODE>
__global__ __launch_bounds__(128) void k_fconv(const float2* __restrict__ in,
                                               float2* __restrict__ out) {
    __shared__ float2 sbuf[4][32 * 32];
    int warp = threadIdx.x >> 5;
    int t = threadIdx.x & 31;
    int r = blockIdx.x * 4 + warp;
    float2* sm = sbuf[warp];

    float2 Wt = g_W1024[t];
    float2 a[32];

#pragma unroll
    for (int n1 = 0; n1 < 32; n1++) {
        int idx = n1 * 32 + t;
        float2 v = make_float2(0.f, 0.f);
        if (idx < 500) {
            v = in[(size_t)r * GN + idx];
            if (MODE) v = cmul(v, g_chirp[idx]);
        }
        a[n1] = v;
    }

    fft32<-1>(a);
    {
        float2 w = make_float2(1.f, 0.f);
#pragma unroll
        for (int k1 = 0; k1 < 32; k1++) {
            a[k1] = cmul(a[k1], w);
            w = cmul(w, Wt);
        }
    }
    // swizzled transpose: store row k1 at column (t ^ k1); load row t at
    // column (n2 ^ t). Conflict-free both ways.
#pragma unroll
    for (int k1 = 0; k1 < 32; k1++) sm[k1 * 32 + (t ^ k1)] = a[k1];
    __syncwarp();
#pragma unroll
    for (int n2 = 0; n2 < 32; n2++) a[n2] = sm[t * 32 + (n2 ^ t)];

    fft32<-1>(a);

    const float2* K = MODE ? g_Kb : g_Kp;
#pragma unroll
    for (int k2 = 0; k2 < 32; k2++) a[k2] = cmul(a[k2], K[k2 * 32 + t]);

    fft32<1>(a);
    {
        float2 w = make_float2(1.f, 0.f);
#pragma unroll
        for (int n2 = 0; n2 < 32; n2++) {
            a[n2] = cmul(a[n2], w);
            w = cmulc(w, Wt);
        }
    }
    __syncwarp();
#pragma unroll
    for (int n2 = 0; n2 < 32; n2++) sm[n2 * 32 + (t ^ n2)] = a[n2];
    __syncwarp();
#pragma unroll
    for (int k1 = 0; k1 < 32; k1++) a[k1] = sm[t * 32 + (k1 ^ t)];

    fft32<1>(a);

    if (MODE == 0) {
#pragma unroll
        for (int n1 = 0; n1 < 32; n1++) {
            int idx = n1 * 32 + t;
            if (idx >= 500 && idx < 1000)
                out[(size_t)(idx - 500) * GN + r] = a[n1];
        }
    } else {
#pragma unroll
        for (int n1 = 0; n1 < 32; n1++) {
            int idx = n1 * 32 + t;
            if (idx < 500)
                out[(size_t)idx * GN + r] = cmul(a[n1], g_chirp[idx]);
        }
    }
}

// ---------------- per-emitter intensity: warp-owned emitter ranges ---------
__global__ __launch_bounds__(128) void k_emit(const int* __restrict__ xyz) {
    __shared__ float2 sfo[GN];
    __shared__ float  stg[GN];
    __shared__ float2 sW[GN];
    int u = blockIdx.x;

    const float2* fo = g_B + (size_t)u * GN;   // FO lives in g_B
    const float*  tg = g_tg + (size_t)u * GN;
    for (int i = threadIdx.x; i < GN; i += 128) {
        sfo[i] = fo[i];
        stg[i] = tg[i];
        sW[i]  = g_W500i[i];
    }
    __syncthreads();

    int lane = threadIdx.x & 31;
    int wid = threadIdx.x >> 5;

    for (int e = wid * 32; e < wid * 32 + 32; e++) {
        int x0 = xyz[e * 3 + 0];
        int z = xyz[e * 3 + 2];
        float xf = (float)(x0 - 100);
        int c = 249 + z;
        int idx = (c * lane) % GN;
        int step = (c * 32) % GN;

        float sx = 0.f, sy = 0.f;
        for (int v = lane; v < GN; v += 32) {
            float arg = stg[v] * xf;  // f32 rounding matches reference
            float nq = rintf(arg * 0.15915494309189535f);
            float rr = fmaf(nq, -6.28125f, arg);
            rr = fmaf(nq, -1.9353072e-3f, rr);
            float sn, cs;
            __sincosf(rr, &sn, &cs);
            float2 f = sfo[v];
            float pr = f.x * cs - f.y * sn;
            float pi = f.x * sn + f.y * cs;
            float2 w = sW[idx];
            sx = fmaf(pr, w.x, sx); sx = fmaf(-pi, w.y, sx);
            sy = fmaf(pr, w.y, sy); sy = fmaf(pi, w.x, sy);
            idx += step; if (idx >= GN) idx -= GN;
        }
#pragma unroll
        for (int o = 16; o > 0; o >>= 1) {
            sx += __shfl_down_sync(0xffffffffu, sx, o);
            sy += __shfl_down_sync(0xffffffffu, sy, o);
        }
        if (lane == 0)
            atomicAdd(&g_intens[e], (sx * sx + sy * sy) * 8e-9f);  // 1/500^3
    }
}

// ---------------- scatter psf patches into canvas --------------------------
__global__ void k_scatter(const int* __restrict__ xyz,
                          const float* __restrict__ psf) {
    int tid = blockIdx.x * blockDim.x + threadIdx.x;
    if (tid >= 128 * 961) return;
    int e = tid / 961, p = tid % 961;
    int b = e >> 6;
    int x0 = xyz[e * 3 + 0];
    int y0 = xyz[e * 3 + 1];
    int z = xyz[e * 3 + 2];
    int r = p / 31, cc = p % 31;
    float val = psf[z * 961 + p] * g_intens[e];
    int row = x0 + r - 15;
    int col = y0 + cc - 15;
    atomicAdd(&g_canvas[b * 40000 + row * 200 + col], val);
}

// ---------------- noise model + output -------------------------------------
__global__ void k_final(const float* __restrict__ ng,
                        const float* __restrict__ np_,
                        float* __restrict__ out) {
    int i = blockIdx.x * blockDim.x + threadIdx.x;
    if (i >= 2 * 200 * 200) return;
    float a = g_canvas[i] / 50000.0f + 100.0f;  // imgs3D + UNIF_BG
    float b = a + 100000.0f;
    float t = fmaf(2.0e8f, ng[i], 3.0e8f);
    float inp = b + t;
    if (inp <= 0.0f) inp = 0.0f;
    float noisy = inp + 100.0f * sqrtf(inp) * np_[i];
    if (noisy <= 10.0f) noisy = 1.0f;
    noisy = fminf(noisy, 4.0e9f);
    out[i] = noisy / 4.0e9f;
}

// ---------------------------------------------------------------------------
extern "C" void kernel_launch(void* const* d_in, const int* in_sizes, int n_in,
                              void* d_out, int out_size) {
    const float*  mask_param = (const float*)d_in[0];
    const int*    xyz        = (const int*)d_in[1];
    // d_in[2] = nphotons (unused by reference)
    const float2* B1         = (const float2*)d_in[3];
    // d_in[4] = Q1 (replaced by separable p-vector)
    const float*  mask_real  = (const float*)d_in[5];
    const float*  gamma_c    = (const float*)d_in[6];
    const float*  psf        = (const float*)d_in[7];
    const float*  ngauss     = (const float*)d_in[8];
    const float*  npoiss     = (const float*)d_in[9];
    float*        out        = (float*)d_out;

    double Kd = 2.0 * 1.33 * 3.14159265358979323846 / 5.61e-7;
    float sK = (float)(Kd * 1e-6);

    float2 *fld, *bA, *bB;
    cudaGetSymbolAddress((void**)&fld, g_field);
    cudaGetSymbolAddress((void**)&bA, g_A);
    cudaGetSymbolAddress((void**)&bB, g_B);

    const int BT = 256;

    // fused setup
    k_prep<<<(GN * GN + BT - 1) / BT, BT>>>(mask_param, mask_real, B1,
                                            gamma_c, sK);

    // kernel-spectrum tables Kp, Kb
    k_tabdft<<<dim3(1024, 2), 128>>>();

    // out = 1e-6 T f T^T (two conv passes), FO = F out F^T (two bluestein)
    k_fconv<0><<<125, 128>>>(fld, bA);
    k_fconv<0><<<125, 128>>>(bA, bB);
    k_fconv<1><<<125, 128>>>(bB, bA);
    k_fconv<1><<<125, 128>>>(bA, bB);   // FO -> g_B

    // per-emitter intensities (4 warps x 32 emitters per block, grid 500)
    k_emit<<<GN, 128>>>(xyz);

    // patches -> canvas
    k_scatter<<<(128 * 961 + BT - 1) / BT, BT>>>(xyz, psf);

    // noise model -> output
    k_final<<<(2 * 200 * 200 + BT - 1) / BT, BT>>>(ngauss, npoiss, out);
}